// round 12
// baseline (speedup 1.0000x reference)
#include <cuda_runtime.h>
#include <cuda_fp16.h>
#include <cstdint>
#include <math.h>

#define NN 16
#define CC 256
#define OO 256
#define HWP 4096
#define NCHUNK 36          // 9 taps x 4 chunks of 64 channels

__device__ __half g_xT[(size_t)NN * HWP * CC];  // NHWC fp16 input
__device__ float g_wB[(size_t)NCHUNK * 9216];   // per chunk: B[256 o][36 words] (32 kpair + 4 pad)

// ---------------- helpers ----------------
__device__ __forceinline__ uint32_t smem_u32(const void* p) {
    uint32_t a;
    asm("{ .reg .u64 t; cvta.to.shared.u64 t, %1; cvt.u32.u64 %0, t; }" : "=r"(a) : "l"(p));
    return a;
}
__device__ __forceinline__ void cp_async16(uint32_t d, const void* s) {
    asm volatile("cp.async.ca.shared.global [%0], [%1], 16;" :: "r"(d), "l"(s));
}
#define CP_COMMIT() asm volatile("cp.async.commit_group;" ::: "memory")
#define CP_WAIT0()  asm volatile("cp.async.wait_group 0;" ::: "memory")

__device__ __forceinline__ __half2 u2h(uint32_t v) { return *(__half2*)&v; }
__device__ __forceinline__ uint32_t h2u(__half2 v) { return *(uint32_t*)&v; }

__device__ __forceinline__ void mma16816(float* c, uint32_t a0, uint32_t a1,
                                         uint32_t a2, uint32_t a3,
                                         uint32_t b0, uint32_t b1) {
    asm volatile(
        "mma.sync.aligned.m16n8k16.row.col.f32.f16.f16.f32 "
        "{%0,%1,%2,%3}, {%4,%5,%6,%7}, {%8,%9}, {%0,%1,%2,%3};"
        : "+f"(c[0]), "+f"(c[1]), "+f"(c[2]), "+f"(c[3])
        : "r"(a0), "r"(a1), "r"(a2), "r"(a3), "r"(b0), "r"(b1));
}

// ---------------- kernel 1: NCHW f32 -> NHWC fp16 ----------------
__global__ void transpose_x_kernel(const float* __restrict__ x) {
    __shared__ float tile[64][33];
    const int n = blockIdx.z, s0 = blockIdx.x * 32, c0 = blockIdx.y * 64;
    const int tx = threadIdx.x, ty = threadIdx.y;   // (32, 8)
    const float* xp = x + (size_t)n * CC * HWP;
#pragma unroll
    for (int j = 0; j < 8; j++)
        tile[ty + j * 8][tx] = xp[(size_t)(c0 + ty + j * 8) * HWP + s0 + tx];
    __syncthreads();
    __half* xt = g_xT + (size_t)n * HWP * CC;
#pragma unroll
    for (int j = 0; j < 4; j++) {
        const int s = ty + j * 8;
        __half2 hv = __floats2half2_rn(tile[2 * tx][s], tile[2 * tx + 1][s]);
        *(__half2*)(xt + (size_t)(s0 + s) * CC + c0 + 2 * tx) = hv;
    }
}

// ---------------- kernel 2: weights fp16, [chunk][o][36] (32 kpair + pad) ----------------
__global__ void wprep_kernel(const float* __restrict__ wdef) {
    int idx = blockIdx.x * blockDim.x + threadIdx.x;
    if (idx >= NCHUNK * 256 * 32) return;
    int p2 = idx & 31, o = (idx >> 5) & 255, chunk = idx >> 13;
    int tap = chunk >> 2, cg4 = chunk & 3;
    int c0 = cg4 * 64 + 2 * p2;
    float w0 = wdef[((size_t)o * CC + c0) * 9 + tap];
    float w1 = wdef[((size_t)o * CC + c0 + 1) * 9 + tap];
    __half2 hp = __halves2half2(__float2half_rn(w0), __float2half_rn(w1));
    g_wB[(size_t)chunk * 9216 + o * 36 + p2] = __uint_as_float(h2u(hp));
}

// ---------------- kernel 3: M=64 tiles, K=64 chunks, 2 CTAs/SM ----------------
// SMEM word offsets
#define W_COORD 0                 // 2 x [64 px][8]  (tap parity) = 1024
#define W_RED   1024              // 256
#define W_A     1280              // 2 x [64 px][36 words] = 4608 (chunk parity)
#define W_B     5888              // 2 x [256 o][36 words] = 18432
#define SMEM_WORDS 24320
#define SMEM_BYTES (SMEM_WORDS * 4)   // 97280

__global__ void __launch_bounds__(256, 2)
deform_mma_kernel(const float* __restrict__ off, const float* __restrict__ wcls,
                  const float* __restrict__ bcls, float* __restrict__ out) {
    extern __shared__ float sm[];
    int* smi = (int*)sm;
    const uint32_t sb = smem_u32(sm);
    const int t = threadIdx.x, lane = t & 31, w = t >> 5;
    const int mg = w >> 2, ng = w & 3;               // 2 m-groups x 4 n-groups
    const int n = blockIdx.x >> 6, pblk = blockIdx.x & 63;
    const int px0 = pblk * 64;
    const int pxt = t >> 2, cs = t & 3;              // gather: 1 px, 16 ch per thread
    const int la = lane & 3, r = lane >> 2;
    const __half* xb = g_xT + (size_t)n * HWP * CC;

    float acc[2][8][4];
#pragma unroll
    for (int a = 0; a < 2; a++)
#pragma unroll
        for (int b = 0; b < 8; b++)
#pragma unroll
            for (int c = 0; c < 4; c++) acc[a][b][c] = 0.f;

#define COORDS(TAP, BASE)                                                        \
    if (t < 64) {                                                                \
        const int gpix = px0 + t, hh = gpix >> 6, wx = gpix & 63;                \
        const float* op = off + (size_t)(n * HWP + gpix) * 18 + 2 * (TAP);       \
        const float dy = op[0], dx = op[1];                                      \
        const float py = (float)(hh + (TAP) / 3 - 1) + dy;                       \
        const float pxx = (float)(wx + (TAP) % 3 - 1) + dx;                      \
        const float y0f = floorf(py), x0f = floorf(pxx);                         \
        const float fy = py - y0f, fx = pxx - x0f;                               \
        const int y0 = (int)y0f, x0 = (int)x0f, y1 = y0 + 1, x1 = x0 + 1;        \
        float w00 = (1.f - fy) * (1.f - fx), w01 = (1.f - fy) * fx;              \
        float w10 = fy * (1.f - fx), w11 = fy * fx;                              \
        if (!((unsigned)y0 < 64u && (unsigned)x0 < 64u)) w00 = 0.f;              \
        if (!((unsigned)y0 < 64u && (unsigned)x1 < 64u)) w01 = 0.f;              \
        if (!((unsigned)y1 < 64u && (unsigned)x0 < 64u)) w10 = 0.f;              \
        if (!((unsigned)y1 < 64u && (unsigned)x1 < 64u)) w11 = 0.f;              \
        const int yc0 = min(max(y0, 0), 63), yc1 = min(max(y1, 0), 63);          \
        const int xc0 = min(max(x0, 0), 63), xc1 = min(max(x1, 0), 63);          \
        smi[(BASE) + t * 8 + 0] = (yc0 * 64 + xc0) * 256;                        \
        smi[(BASE) + t * 8 + 1] = (yc0 * 64 + xc1) * 256;                        \
        smi[(BASE) + t * 8 + 2] = (yc1 * 64 + xc0) * 256;                        \
        smi[(BASE) + t * 8 + 3] = (yc1 * 64 + xc1) * 256;                        \
        sm[(BASE) + t * 8 + 4] = w00; sm[(BASE) + t * 8 + 5] = w01;              \
        sm[(BASE) + t * 8 + 6] = w10; sm[(BASE) + t * 8 + 7] = w11;              \
    }

#define STAGE_B(CH, BUF) {                                                       \
        const float4* src = (const float4*)(g_wB + (size_t)(CH) * 9216);         \
        const uint32_t db = sb + (W_B + (BUF) * 9216) * 4;                       \
        _Pragma("unroll")                                                        \
        for (int i = 0; i < 9; i++)                                              \
            cp_async16(db + (uint32_t)(t + (i << 8)) * 16, src + t + (i << 8));  \
    }

// both phases gathered up front: 8 LDG.128 with a full chunk of mma as cover
#define GATHER_ALL(CBASE, CB) {                                                  \
        const int choff = (CB) + cs * 16;                                        \
        const int* ci = smi + (CBASE) + pxt * 8;                                 \
        const float* cf = sm + (CBASE) + pxt * 8;                                \
        wh[0] = __float2half2_rn(cf[4]);                                         \
        wh[1] = __float2half2_rn(cf[5]);                                         \
        wh[2] = __float2half2_rn(cf[6]);                                         \
        wh[3] = __float2half2_rn(cf[7]);                                         \
        ga[0][0] = *(const uint4*)(xb + ci[0] + choff);                          \
        ga[0][1] = *(const uint4*)(xb + ci[1] + choff);                          \
        ga[0][2] = *(const uint4*)(xb + ci[2] + choff);                          \
        ga[0][3] = *(const uint4*)(xb + ci[3] + choff);                          \
        ga[1][0] = *(const uint4*)(xb + ci[0] + choff + 8);                      \
        ga[1][1] = *(const uint4*)(xb + ci[1] + choff + 8);                      \
        ga[1][2] = *(const uint4*)(xb + ci[2] + choff + 8);                      \
        ga[1][3] = *(const uint4*)(xb + ci[3] + choff + 8);                      \
    }

// combine -> A[px][36]: 4 contiguous words, one STS.128, conflict-free
#define COMBINE_PHASE(HF, ABASE) {                                               \
        __half2 v0 = __hmul2(u2h(ga[HF][0].x), wh[0]);                           \
        v0 = __hfma2(u2h(ga[HF][1].x), wh[1], v0);                               \
        v0 = __hfma2(u2h(ga[HF][2].x), wh[2], v0);                               \
        v0 = __hfma2(u2h(ga[HF][3].x), wh[3], v0);                               \
        __half2 v1 = __hmul2(u2h(ga[HF][0].y), wh[0]);                           \
        v1 = __hfma2(u2h(ga[HF][1].y), wh[1], v1);                               \
        v1 = __hfma2(u2h(ga[HF][2].y), wh[2], v1);                               \
        v1 = __hfma2(u2h(ga[HF][3].y), wh[3], v1);                               \
        __half2 v2 = __hmul2(u2h(ga[HF][0].z), wh[0]);                           \
        v2 = __hfma2(u2h(ga[HF][1].z), wh[1], v2);                               \
        v2 = __hfma2(u2h(ga[HF][2].z), wh[2], v2);                               \
        v2 = __hfma2(u2h(ga[HF][3].z), wh[3], v2);                               \
        __half2 v3 = __hmul2(u2h(ga[HF][0].w), wh[0]);                           \
        v3 = __hfma2(u2h(ga[HF][1].w), wh[1], v3);                               \
        v3 = __hfma2(u2h(ga[HF][2].w), wh[2], v3);                               \
        v3 = __hfma2(u2h(ga[HF][3].w), wh[3], v3);                               \
        float4 pk;                                                               \
        pk.x = __uint_as_float(h2u(v0)); pk.y = __uint_as_float(h2u(v1));        \
        pk.z = __uint_as_float(h2u(v2)); pk.w = __uint_as_float(h2u(v3));        \
        *(float4*)(sm + (ABASE) + pxt * 36 + cs * 8 + (HF) * 4) = pk;            \
    }

#define MMA_KT(KT, ABASE, BBASE) {                                               \
        const uint32_t* Ah = (const uint32_t*)(sm + (ABASE));                    \
        const uint32_t* Bh = (const uint32_t*)(sm + (BBASE));                    \
        uint32_t af[2][4];                                                       \
        _Pragma("unroll")                                                        \
        for (int mt = 0; mt < 2; mt++) {                                         \
            const int base = (mg * 32 + mt * 16 + r) * 36 + (KT) * 8 + la;       \
            af[mt][0] = Ah[base];       af[mt][1] = Ah[base + 288];              \
            af[mt][2] = Ah[base + 4];   af[mt][3] = Ah[base + 292];              \
        }                                                                        \
        _Pragma("unroll")                                                        \
        for (int nt = 0; nt < 8; nt++) {                                         \
            const int ob = (ng * 64 + nt * 8 + r) * 36 + (KT) * 8 + la;          \
            const uint32_t bh0 = Bh[ob], bh1 = Bh[ob + 4];                       \
            _Pragma("unroll")                                                    \
            for (int mt = 0; mt < 2; mt++) {                                     \
                mma16816(acc[mt][nt], af[mt][0], af[mt][1], af[mt][2], af[mt][3], bh0, bh1); \
            }                                                                    \
        }                                                                        \
    }

    uint4 ga[2][4];
    __half2 wh[4];

    // ---------------- prologue ----------------
    COORDS(0, W_COORD);
    __syncthreads();
    STAGE_B(0, 0);
    CP_COMMIT();
    GATHER_ALL(W_COORD, 0);
    COMBINE_PHASE(0, W_A);
    COMBINE_PHASE(1, W_A);
    CP_WAIT0();
    __syncthreads();

    // ---------------- main loop ----------------
#pragma unroll 1
    for (int k = 0; k < NCHUNK; ++k) {
        const int buf = k & 1, nbuf = buf ^ 1;
        const bool nx = (k + 1 < NCHUNK);
        const int abase = W_A + buf * 2304, bbase = W_B + buf * 9216;
        const int anext = W_A + nbuf * 2304;
        const int tapN = (k + 1) >> 2;
        const int cbase = W_COORD + (tapN & 1) * 512;
        const int cbch = ((k + 1) & 3) << 6;

        if (nx) STAGE_B(k + 1, nbuf);
        CP_COMMIT();

        if (nx) GATHER_ALL(cbase, cbch);

        MMA_KT(0, abase, bbase);
        MMA_KT(1, abase, bbase);
        MMA_KT(2, abase, bbase);
        MMA_KT(3, abase, bbase);

        if (nx) { COMBINE_PHASE(0, anext); COMBINE_PHASE(1, anext); }

        if (((k + 2) & 3) == 0 && (k + 2) < NCHUNK) {
            const int t2 = (k + 2) >> 2;
            COORDS(t2, W_COORD + (t2 & 1) * 512);
        }
        CP_WAIT0();
        __syncthreads();
    }

    // ---------------- epilogue: relu + wcls dot, reduce over o ----------------
    {
        float s[2][2];
#pragma unroll
        for (int mt = 0; mt < 2; mt++) { s[mt][0] = 0.f; s[mt][1] = 0.f; }
#pragma unroll
        for (int nt = 0; nt < 8; nt++) {
            const int col = ng * 64 + nt * 8 + 2 * la;
            const float wc0 = __ldg(&wcls[col]), wc1 = __ldg(&wcls[col + 1]);
#pragma unroll
            for (int mt = 0; mt < 2; mt++) {
                s[mt][0] += wc0 * fmaxf(acc[mt][nt][0], 0.f) + wc1 * fmaxf(acc[mt][nt][1], 0.f);
                s[mt][1] += wc0 * fmaxf(acc[mt][nt][2], 0.f) + wc1 * fmaxf(acc[mt][nt][3], 0.f);
            }
        }
#pragma unroll
        for (int d = 1; d <= 2; d <<= 1)
#pragma unroll
            for (int mt = 0; mt < 2; mt++) {
                s[mt][0] += __shfl_xor_sync(0xFFFFFFFFu, s[mt][0], d);
                s[mt][1] += __shfl_xor_sync(0xFFFFFFFFu, s[mt][1], d);
            }
        __syncthreads();
        if (la == 0) {
#pragma unroll
            for (int mt = 0; mt < 2; mt++) {
                const int px = mg * 32 + mt * 16 + r;
                sm[W_RED + ng * 64 + px] = s[mt][0];
                sm[W_RED + ng * 64 + px + 8] = s[mt][1];
            }
        }
        __syncthreads();
        if (t < 64) {
            out[(size_t)n * HWP + px0 + t] =
                sm[W_RED + t] + sm[W_RED + 64 + t] +
                sm[W_RED + 128 + t] + sm[W_RED + 192 + t] + bcls[0];
        }
    }
}

// ---------------- launch ----------------
extern "C" void kernel_launch(void* const* d_in, const int* in_sizes, int n_in,
                              void* d_out, int out_size) {
    const float* x      = (const float*)d_in[0];
    const float* offset = (const float*)d_in[1];
    const float* w_def  = (const float*)d_in[2];
    const float* w_cls  = (const float*)d_in[3];
    const float* b_cls  = (const float*)d_in[4];
    float* out = (float*)d_out;

    dim3 g1(HWP / 32, CC / 64, NN), b1(32, 8);
    transpose_x_kernel<<<g1, b1>>>(x);
    wprep_kernel<<<(NCHUNK * 256 * 32 + 255) / 256, 256>>>(w_def);

    cudaFuncSetAttribute(deform_mma_kernel,
                         cudaFuncAttributeMaxDynamicSharedMemorySize, SMEM_BYTES);
    deform_mma_kernel<<<NN * 64, 256, SMEM_BYTES>>>(offset, w_cls, b_cls, out);
}

// round 14
// speedup vs baseline: 1.0683x; 1.0683x over previous
#include <cuda_runtime.h>
#include <cuda_fp16.h>
#include <cstdint>
#include <math.h>

#define NN 16
#define CC 256
#define OO 256
#define HWP 4096
#define NCHUNK 36          // 9 taps x 4 chunks of 64 channels

__device__ __half g_xT[(size_t)NN * HWP * CC];  // NHWC fp16 input
__device__ float g_wB[(size_t)NCHUNK * 8192];   // per chunk: B[256 o][32 words] PACKED (pad added on store)

// ---------------- helpers ----------------
__device__ __forceinline__ uint32_t smem_u32(const void* p) {
    uint32_t a;
    asm("{ .reg .u64 t; cvta.to.shared.u64 t, %1; cvt.u32.u64 %0, t; }" : "=r"(a) : "l"(p));
    return a;
}
__device__ __forceinline__ void cp_async16(uint32_t d, const void* s) {
    asm volatile("cp.async.ca.shared.global [%0], [%1], 16;" :: "r"(d), "l"(s));
}
#define CP_COMMIT() asm volatile("cp.async.commit_group;" ::: "memory")
#define CP_WAIT0()  asm volatile("cp.async.wait_group 0;" ::: "memory")

__device__ __forceinline__ __half2 u2h(uint32_t v) { return *(__half2*)&v; }
__device__ __forceinline__ uint32_t h2u(__half2 v) { return *(uint32_t*)&v; }

__device__ __forceinline__ void mma16816(float* c, uint32_t a0, uint32_t a1,
                                         uint32_t a2, uint32_t a3,
                                         uint32_t b0, uint32_t b1) {
    asm volatile(
        "mma.sync.aligned.m16n8k16.row.col.f32.f16.f16.f32 "
        "{%0,%1,%2,%3}, {%4,%5,%6,%7}, {%8,%9}, {%0,%1,%2,%3};"
        : "+f"(c[0]), "+f"(c[1]), "+f"(c[2]), "+f"(c[3])
        : "r"(a0), "r"(a1), "r"(a2), "r"(a3), "r"(b0), "r"(b1));
}

// ---------------- kernel 1: NCHW f32 -> NHWC fp16 ----------------
__global__ void transpose_x_kernel(const float* __restrict__ x) {
    __shared__ float tile[64][33];
    const int n = blockIdx.z, s0 = blockIdx.x * 32, c0 = blockIdx.y * 64;
    const int tx = threadIdx.x, ty = threadIdx.y;   // (32, 8)
    const float* xp = x + (size_t)n * CC * HWP;
#pragma unroll
    for (int j = 0; j < 8; j++)
        tile[ty + j * 8][tx] = xp[(size_t)(c0 + ty + j * 8) * HWP + s0 + tx];
    __syncthreads();
    __half* xt = g_xT + (size_t)n * HWP * CC;
#pragma unroll
    for (int j = 0; j < 4; j++) {
        const int s = ty + j * 8;
        __half2 hv = __floats2half2_rn(tile[2 * tx][s], tile[2 * tx + 1][s]);
        *(__half2*)(xt + (size_t)(s0 + s) * CC + c0 + 2 * tx) = hv;
    }
}

// ---------------- kernel 2: weights fp16, PACKED [chunk][o][32 words] ----------------
__global__ void wprep_kernel(const float* __restrict__ wdef) {
    int idx = blockIdx.x * blockDim.x + threadIdx.x;
    if (idx >= NCHUNK * 256 * 32) return;
    int p2 = idx & 31, o = (idx >> 5) & 255, chunk = idx >> 13;
    int tap = chunk >> 2, cg4 = chunk & 3;
    int c0 = cg4 * 64 + 2 * p2;
    float w0 = wdef[((size_t)o * CC + c0) * 9 + tap];
    float w1 = wdef[((size_t)o * CC + c0 + 1) * 9 + tap];
    __half2 hp = __halves2half2(__float2half_rn(w0), __float2half_rn(w1));
    g_wB[(size_t)chunk * 8192 + o * 32 + p2] = __uint_as_float(h2u(hp));
}

// ---------------- kernel 3: M=64 tiles, K=64 chunks, 2 CTAs/SM ----------------
// SMEM word offsets
#define W_COORD 0                 // 2 x [64 px][8]  (tap parity) = 1024
#define W_RED   1024              // 256
#define W_A     1280              // 2 x [64 px][36 words] = 4608 (chunk parity)
#define W_B     5888              // 2 x [256 o][36 words] = 18432
#define SMEM_WORDS 24320
#define SMEM_BYTES (SMEM_WORDS * 4)   // 97280

__global__ void __launch_bounds__(256, 2)
deform_mma_kernel(const float* __restrict__ off, const float* __restrict__ wcls,
                  const float* __restrict__ bcls, float* __restrict__ out) {
    extern __shared__ float sm[];
    int* smi = (int*)sm;
    const uint32_t sb = smem_u32(sm);
    const int t = threadIdx.x, lane = t & 31, w = t >> 5;
    const int mg = w >> 2, ng = w & 3;               // 2 m-groups x 4 n-groups
    const int n = blockIdx.x >> 6, pblk = blockIdx.x & 63;
    const int px0 = pblk * 64;
    const int pxt = t >> 2, cs = t & 3;              // gather: 1 px, 16 ch per thread
    const int la = lane & 3, r = lane >> 2;
    const __half* xb = g_xT + (size_t)n * HWP * CC;

    float acc[2][8][4];
#pragma unroll
    for (int a = 0; a < 2; a++)
#pragma unroll
        for (int b = 0; b < 8; b++)
#pragma unroll
            for (int c = 0; c < 4; c++) acc[a][b][c] = 0.f;

#define COORDS(TAP, BASE)                                                        \
    if (t < 64) {                                                                \
        const int gpix = px0 + t, hh = gpix >> 6, wx = gpix & 63;                \
        const float* op = off + (size_t)(n * HWP + gpix) * 18 + 2 * (TAP);       \
        const float dy = op[0], dx = op[1];                                      \
        const float py = (float)(hh + (TAP) / 3 - 1) + dy;                       \
        const float pxx = (float)(wx + (TAP) % 3 - 1) + dx;                      \
        const float y0f = floorf(py), x0f = floorf(pxx);                         \
        const float fy = py - y0f, fx = pxx - x0f;                               \
        const int y0 = (int)y0f, x0 = (int)x0f, y1 = y0 + 1, x1 = x0 + 1;        \
        float w00 = (1.f - fy) * (1.f - fx), w01 = (1.f - fy) * fx;              \
        float w10 = fy * (1.f - fx), w11 = fy * fx;                              \
        if (!((unsigned)y0 < 64u && (unsigned)x0 < 64u)) w00 = 0.f;              \
        if (!((unsigned)y0 < 64u && (unsigned)x1 < 64u)) w01 = 0.f;              \
        if (!((unsigned)y1 < 64u && (unsigned)x0 < 64u)) w10 = 0.f;              \
        if (!((unsigned)y1 < 64u && (unsigned)x1 < 64u)) w11 = 0.f;              \
        const int yc0 = min(max(y0, 0), 63), yc1 = min(max(y1, 0), 63);          \
        const int xc0 = min(max(x0, 0), 63), xc1 = min(max(x1, 0), 63);          \
        smi[(BASE) + t * 8 + 0] = (yc0 * 64 + xc0) * 256;                        \
        smi[(BASE) + t * 8 + 1] = (yc0 * 64 + xc1) * 256;                        \
        smi[(BASE) + t * 8 + 2] = (yc1 * 64 + xc0) * 256;                        \
        smi[(BASE) + t * 8 + 3] = (yc1 * 64 + xc1) * 256;                        \
        sm[(BASE) + t * 8 + 4] = w00; sm[(BASE) + t * 8 + 5] = w01;              \
        sm[(BASE) + t * 8 + 6] = w10; sm[(BASE) + t * 8 + 7] = w11;              \
    }

// packed gmem (row*32 words) -> padded smem (row*36 words); 2048 cp.async16
#define STAGE_B(CH, BUF) {                                                       \
        const float4* src = (const float4*)(g_wB + (size_t)(CH) * 8192);         \
        const uint32_t db = sb + (W_B + (BUF) * 9216) * 4;                       \
        _Pragma("unroll")                                                        \
        for (int i = 0; i < 8; i++) {                                            \
            const int idx = t + (i << 8);                                        \
            const int row = idx >> 3, w4 = (idx & 7) << 2;                       \
            cp_async16(db + (uint32_t)(row * 36 + w4) * 4, src + idx);           \
        }                                                                        \
    }

// phase HF loads 8 channels (1 uint4 = 16B) per corner at ch = cs*16 + HF*8
#define GATHER_PHASE(HF, CBASE, CB) {                                            \
        const int choff = (CB) + cs * 16 + (HF) * 8;                             \
        const int* ci = smi + (CBASE) + pxt * 8;                                 \
        const float* cf = sm + (CBASE) + pxt * 8;                                \
        wh[0] = __float2half2_rn(cf[4]);                                         \
        wh[1] = __float2half2_rn(cf[5]);                                         \
        wh[2] = __float2half2_rn(cf[6]);                                         \
        wh[3] = __float2half2_rn(cf[7]);                                         \
        ga[0] = *(const uint4*)(xb + ci[0] + choff);                             \
        ga[1] = *(const uint4*)(xb + ci[1] + choff);                             \
        ga[2] = *(const uint4*)(xb + ci[2] + choff);                             \
        ga[3] = *(const uint4*)(xb + ci[3] + choff);                             \
    }

// combine -> A[px][36]: 4 contiguous words, one STS.128, conflict-free
#define COMBINE_PHASE(HF, ABASE) {                                               \
        __half2 v0 = __hmul2(u2h(ga[0].x), wh[0]);                               \
        v0 = __hfma2(u2h(ga[1].x), wh[1], v0);                                   \
        v0 = __hfma2(u2h(ga[2].x), wh[2], v0);                                   \
        v0 = __hfma2(u2h(ga[3].x), wh[3], v0);                                   \
        __half2 v1 = __hmul2(u2h(ga[0].y), wh[0]);                               \
        v1 = __hfma2(u2h(ga[1].y), wh[1], v1);                                   \
        v1 = __hfma2(u2h(ga[2].y), wh[2], v1);                                   \
        v1 = __hfma2(u2h(ga[3].y), wh[3], v1);                                   \
        __half2 v2 = __hmul2(u2h(ga[0].z), wh[0]);                               \
        v2 = __hfma2(u2h(ga[1].z), wh[1], v2);                                   \
        v2 = __hfma2(u2h(ga[2].z), wh[2], v2);                                   \
        v2 = __hfma2(u2h(ga[3].z), wh[3], v2);                                   \
        __half2 v3 = __hmul2(u2h(ga[0].w), wh[0]);                               \
        v3 = __hfma2(u2h(ga[1].w), wh[1], v3);                                   \
        v3 = __hfma2(u2h(ga[2].w), wh[2], v3);                                   \
        v3 = __hfma2(u2h(ga[3].w), wh[3], v3);                                   \
        float4 pk;                                                               \
        pk.x = __uint_as_float(h2u(v0)); pk.y = __uint_as_float(h2u(v1));        \
        pk.z = __uint_as_float(h2u(v2)); pk.w = __uint_as_float(h2u(v3));        \
        *(float4*)(sm + (ABASE) + pxt * 36 + cs * 8 + (HF) * 4) = pk;            \
    }

#define MMA_KT(KT, ABASE, BBASE) {                                               \
        const uint32_t* Ah = (const uint32_t*)(sm + (ABASE));                    \
        const uint32_t* Bh = (const uint32_t*)(sm + (BBASE));                    \
        uint32_t af[2][4];                                                       \
        _Pragma("unroll")                                                        \
        for (int mt = 0; mt < 2; mt++) {                                         \
            const int base = (mg * 32 + mt * 16 + r) * 36 + (KT) * 8 + la;       \
            af[mt][0] = Ah[base];       af[mt][1] = Ah[base + 288];              \
            af[mt][2] = Ah[base + 4];   af[mt][3] = Ah[base + 292];              \
        }                                                                        \
        _Pragma("unroll")                                                        \
        for (int nt = 0; nt < 8; nt++) {                                         \
            const int ob = (ng * 64 + nt * 8 + r) * 36 + (KT) * 8 + la;          \
            const uint32_t bh0 = Bh[ob], bh1 = Bh[ob + 4];                       \
            _Pragma("unroll")                                                    \
            for (int mt = 0; mt < 2; mt++) {                                     \
                mma16816(acc[mt][nt], af[mt][0], af[mt][1], af[mt][2], af[mt][3], bh0, bh1); \
            }                                                                    \
        }                                                                        \
    }

    uint4 ga[4];
    __half2 wh[4];

    // ---------------- prologue ----------------
    COORDS(0, W_COORD);
    __syncthreads();
    STAGE_B(0, 0);
    CP_COMMIT();
    GATHER_PHASE(0, W_COORD, 0);
    COMBINE_PHASE(0, W_A);
    GATHER_PHASE(1, W_COORD, 0);
    COMBINE_PHASE(1, W_A);
    CP_WAIT0();
    __syncthreads();

    // ---------------- main loop ----------------
#pragma unroll 1
    for (int k = 0; k < NCHUNK; ++k) {
        const int buf = k & 1, nbuf = buf ^ 1;
        const bool nx = (k + 1 < NCHUNK);
        const int abase = W_A + buf * 2304, bbase = W_B + buf * 9216;
        const int anext = W_A + nbuf * 2304;
        const int tapN = (k + 1) >> 2;
        const int cbase = W_COORD + (tapN & 1) * 512;
        const int cbch = ((k + 1) & 3) << 6;

        if (nx) STAGE_B(k + 1, nbuf);
        CP_COMMIT();

        if (nx) GATHER_PHASE(0, cbase, cbch);
        MMA_KT(0, abase, bbase);
        MMA_KT(1, abase, bbase);
        if (nx) COMBINE_PHASE(0, anext);

        if (nx) GATHER_PHASE(1, cbase, cbch);
        MMA_KT(2, abase, bbase);
        MMA_KT(3, abase, bbase);
        if (nx) COMBINE_PHASE(1, anext);

        if (((k + 2) & 3) == 0 && (k + 2) < NCHUNK) {
            const int t2 = (k + 2) >> 2;
            COORDS(t2, W_COORD + (t2 & 1) * 512);
        }
        CP_WAIT0();
        __syncthreads();
    }

    // ---------------- epilogue: relu + wcls dot, reduce over o ----------------
    {
        float s[2][2];
#pragma unroll
        for (int mt = 0; mt < 2; mt++) { s[mt][0] = 0.f; s[mt][1] = 0.f; }
#pragma unroll
        for (int nt = 0; nt < 8; nt++) {
            const int col = ng * 64 + nt * 8 + 2 * la;
            const float wc0 = __ldg(&wcls[col]), wc1 = __ldg(&wcls[col + 1]);
#pragma unroll
            for (int mt = 0; mt < 2; mt++) {
                s[mt][0] += wc0 * fmaxf(acc[mt][nt][0], 0.f) + wc1 * fmaxf(acc[mt][nt][1], 0.f);
                s[mt][1] += wc0 * fmaxf(acc[mt][nt][2], 0.f) + wc1 * fmaxf(acc[mt][nt][3], 0.f);
            }
        }
#pragma unroll
        for (int d = 1; d <= 2; d <<= 1)
#pragma unroll
            for (int mt = 0; mt < 2; mt++) {
                s[mt][0] += __shfl_xor_sync(0xFFFFFFFFu, s[mt][0], d);
                s[mt][1] += __shfl_xor_sync(0xFFFFFFFFu, s[mt][1], d);
            }
        __syncthreads();
        if (la == 0) {
#pragma unroll
            for (int mt = 0; mt < 2; mt++) {
                const int px = mg * 32 + mt * 16 + r;
                sm[W_RED + ng * 64 + px] = s[mt][0];
                sm[W_RED + ng * 64 + px + 8] = s[mt][1];
            }
        }
        __syncthreads();
        if (t < 64) {
            out[(size_t)n * HWP + px0 + t] =
                sm[W_RED + t] + sm[W_RED + 64 + t] +
                sm[W_RED + 128 + t] + sm[W_RED + 192 + t] + bcls[0];
        }
    }
}

// ---------------- launch ----------------
extern "C" void kernel_launch(void* const* d_in, const int* in_sizes, int n_in,
                              void* d_out, int out_size) {
    const float* x      = (const float*)d_in[0];
    const float* offset = (const float*)d_in[1];
    const float* w_def  = (const float*)d_in[2];
    const float* w_cls  = (const float*)d_in[3];
    const float* b_cls  = (const float*)d_in[4];
    float* out = (float*)d_out;

    dim3 g1(HWP / 32, CC / 64, NN), b1(32, 8);
    transpose_x_kernel<<<g1, b1>>>(x);
    wprep_kernel<<<(NCHUNK * 256 * 32 + 255) / 256, 256>>>(w_def);

    cudaFuncSetAttribute(deform_mma_kernel,
                         cudaFuncAttributeMaxDynamicSharedMemorySize, SMEM_BYTES);
    deform_mma_kernel<<<NN * 64, 256, SMEM_BYTES>>>(offset, w_cls, b_cls, out);
}